// round 3
// baseline (speedup 1.0000x reference)
#include <cuda_runtime.h>
#include <cstddef>

#define B    512
#define P    256
#define T    128
#define E    300
#define H    256
#define NC   64
#define NO   256
#define VOC  10000
#define G4   1024   // 4H (LSTM gates)
#define G3   768    // 3H (GRU gates)
#define INDC 856    // H + 2E (GRU input width)

// ---------------- scratch (device globals; no allocations allowed) ----------------
__device__ float g_EWb[VOC * G4];           // enc_embed @ Wih_p^T + bias (PERMUTED gate layout)
__device__ float g_CWf[NC * NO * G3];       // choice_tables @ W_ch^T + idxC + b_ih
__device__ float g_idxC[NC * G3];
__device__ float g_progC[B * G3];           // prog_emb @ W_prog^T
__device__ float g_hA[B * H];               // LSTM hidden (ping)
__device__ float g_hB[B * H];               // LSTM hidden (pong)
__device__ float g_c[B * H];                // LSTM cell
__device__ float g_hdec[B * H];             // GRU hidden
__device__ float g_hn[B * H];               // batch-normalized GRU hidden
__device__ float g_gg[B * G3];              // GRU recurrent gates (hn @ W_hh^T + b_hh)
__device__ float g_hall[(T - 1) * B * H];   // all decoder hiddens
__device__ float g_Wih_p[G4 * E];           // lstm W_ih, gate-interleaved rows (f*4+g)
__device__ float g_Whh_p[G4 * H];           // lstm W_hh, gate-interleaved rows
__device__ float g_bias2p[G4];              // (b_ih + b_hh), gate-interleaved

// ---------------- generic SGEMM:  C[m,n] = sum_k A[m,k] * W[n, woff+k] (+bias[n]) ----------------
__global__ void sgemm_nt(float* __restrict__ C,
                         const float* __restrict__ A, int lda,
                         const float* __restrict__ W, int ldw, int woff,
                         int M, int N, int K,
                         const float* __restrict__ bias)
{
    __shared__ float As[16][68];
    __shared__ float Ws[16][68];
    const int tid = threadIdx.x;
    const int tx = tid & 15, ty = tid >> 4;
    const int m0 = blockIdx.y * 64, n0 = blockIdx.x * 64;
    const int lr = tid >> 2;          // 0..63
    const int lk = (tid & 3) * 4;     // 0,4,8,12

    float acc[4][4] = {};

    for (int kk = 0; kk < K; kk += 16) {
        {
            const int m = m0 + lr;
            const float* ap = A + (size_t)m * lda + kk + lk;
            #pragma unroll
            for (int i = 0; i < 4; i++) {
                const int k = kk + lk + i;
                As[lk + i][lr] = (m < M && k < K) ? ap[i] : 0.f;
            }
            const int n = n0 + lr;
            const float* wp = W + (size_t)n * ldw + woff + kk + lk;
            #pragma unroll
            for (int i = 0; i < 4; i++) {
                const int k = kk + lk + i;
                Ws[lk + i][lr] = (n < N && k < K) ? wp[i] : 0.f;
            }
        }
        __syncthreads();
        #pragma unroll
        for (int kt = 0; kt < 16; kt++) {
            const float4 a4 = *(const float4*)&As[kt][ty * 4];
            const float4 b4 = *(const float4*)&Ws[kt][tx * 4];
            const float av[4] = {a4.x, a4.y, a4.z, a4.w};
            const float bv[4] = {b4.x, b4.y, b4.z, b4.w};
            #pragma unroll
            for (int i = 0; i < 4; i++)
                #pragma unroll
                for (int j = 0; j < 4; j++)
                    acc[i][j] += av[i] * bv[j];
        }
        __syncthreads();
    }

    #pragma unroll
    for (int i = 0; i < 4; i++) {
        const int m = m0 + ty * 4 + i;
        if (m < M) {
            #pragma unroll
            for (int j = 0; j < 4; j++) {
                const int n = n0 + tx * 4 + j;
                float v = acc[i][j];
                if (bias) v += bias[n];
                C[(size_t)m * N + n] = v;
            }
        }
    }
}

// ---------------- permute LSTM weights to gate-interleaved layout ----------------
// n' = f*4 + gate  <->  n = gate*H + f
__global__ void k_permute(const float* __restrict__ Wih, const float* __restrict__ Whh,
                          const float* __restrict__ bih, const float* __restrict__ bhh)
{
    const int id = blockIdx.x * 256 + threadIdx.x;
    if (id < G4 * E) {
        const int np = id / E, k = id - np * E;
        const int f = np >> 2, g = np & 3;
        g_Wih_p[id] = Wih[(g * H + f) * E + k];
    }
    if (id < G4 * H) {
        const int np = id / H, k = id - np * H;
        const int f = np >> 2, g = np & 3;
        g_Whh_p[id] = Whh[(g * H + f) * H + k];
    }
    if (id < G4) {
        const int f = id >> 2, g = id & 3;
        g_bias2p[id] = bih[g * H + f] + bhh[g * H + f];
    }
}

// ---------------- init states ----------------
__global__ void k_init(const float* __restrict__ h0, const float* __restrict__ c0,
                       const float* __restrict__ hd0)
{
    const int i = blockIdx.x * 256 + threadIdx.x;
    if (i < B * H) {
        g_hA[i] = h0[i];
        g_c[i] = c0[i];
        g_hdec[i] = hd0[i];
    }
}

// ---------------- fold idxC into CWf ----------------
__global__ void k_cwf_fix()
{
    const size_t total = (size_t)NC * NO * G3;
    const size_t id = (size_t)blockIdx.x * 256 + threadIdx.x;
    if (id >= total) return;
    const int n = (int)(id % G3);
    const int m = (int)(id / G3);
    const int p = m / NO;
    g_CWf[id] += g_idxC[p * G3 + n];
}

// ---------------- fused LSTM step: gates GEMM (permuted) + elementwise update ----------------
// grid (G4/64=16, B/64=8), 256 threads. Reads hin, writes hout + g_c.
__global__ void k_lstm_step(const float* __restrict__ hin, float* __restrict__ hout,
                            int t, const int* __restrict__ program,
                            const int* __restrict__ plen)
{
    __shared__ float As[16][68];
    __shared__ float Ws[16][68];
    const int tid = threadIdx.x;
    const int tx = tid & 15, ty = tid >> 4;
    const int m0 = blockIdx.y * 64, n0 = blockIdx.x * 64;
    const int lr = tid >> 2;
    const int lk = (tid & 3) * 4;

    float acc[4][4] = {};

    #pragma unroll 1
    for (int kk = 0; kk < H; kk += 16) {
        {
            const float4 a4 = *(const float4*)(hin + (size_t)(m0 + lr) * H + kk + lk);
            As[lk + 0][lr] = a4.x; As[lk + 1][lr] = a4.y;
            As[lk + 2][lr] = a4.z; As[lk + 3][lr] = a4.w;
            const float4 w4 = *(const float4*)(g_Whh_p + (size_t)(n0 + lr) * H + kk + lk);
            Ws[lk + 0][lr] = w4.x; Ws[lk + 1][lr] = w4.y;
            Ws[lk + 2][lr] = w4.z; Ws[lk + 3][lr] = w4.w;
        }
        __syncthreads();
        #pragma unroll
        for (int kt = 0; kt < 16; kt++) {
            const float4 a4 = *(const float4*)&As[kt][ty * 4];
            const float4 b4 = *(const float4*)&Ws[kt][tx * 4];
            const float av[4] = {a4.x, a4.y, a4.z, a4.w};
            const float bv[4] = {b4.x, b4.y, b4.z, b4.w};
            #pragma unroll
            for (int i = 0; i < 4; i++)
                #pragma unroll
                for (int j = 0; j < 4; j++)
                    acc[i][j] += av[i] * bv[j];
        }
        __syncthreads();
    }

    // epilogue: 4 consecutive permuted columns = gates (i,f,g,o) of feature f
    const int n = n0 + tx * 4;
    const int f = n >> 2;
    #pragma unroll
    for (int i = 0; i < 4; i++) {
        const int b = m0 + ty * 4 + i;
        if (t < plen[b]) {
            const int pid = program[b * P + t];
            const float4 ew = *(const float4*)(g_EWb + (size_t)pid * G4 + n);
            const float gi = acc[i][0] + ew.x;
            const float gf = acc[i][1] + ew.y;
            const float gg = acc[i][2] + ew.z;
            const float go = acc[i][3] + ew.w;
            const float ig = 1.f / (1.f + expf(-gi));
            const float fg = 1.f / (1.f + expf(-gf));
            const float og = 1.f / (1.f + expf(-go));
            const float c = fg * g_c[b * H + f] + ig * tanhf(gg);
            g_c[b * H + f] = c;
            hout[b * H + f] = og * tanhf(c);
        } else {
            hout[b * H + f] = hin[b * H + f];   // frozen state carried forward
        }
    }
}

// ---------------- BatchNorm (batch stats), coalesced ----------------
// grid 8 blocks x 256 threads; block handles 32 features, 8 batch-groups of 64.
__global__ void k_bn(const float* __restrict__ gamma, const float* __restrict__ beta)
{
    const int lf = threadIdx.x & 31;
    const int f = blockIdx.x * 32 + lf;
    const int g = threadIdx.x >> 5;     // 0..7
    __shared__ float ss[8][32], ss2[8][32];
    __shared__ float sm_mean[32], sm_scale[32];

    float s = 0.f, s2 = 0.f;
    #pragma unroll 4
    for (int b = g * 64; b < g * 64 + 64; b++) {
        const float v = g_hdec[b * H + f];
        s += v; s2 += v * v;
    }
    ss[g][lf] = s; ss2[g][lf] = s2;
    __syncthreads();
    if (g == 0) {
        float ts = 0.f, ts2 = 0.f;
        #pragma unroll
        for (int j = 0; j < 8; j++) { ts += ss[j][lf]; ts2 += ss2[j][lf]; }
        const float mean = ts * (1.f / 512.f);
        const float var = ts2 * (1.f / 512.f) - mean * mean;
        sm_mean[lf] = mean;
        sm_scale[lf] = rsqrtf(var + 1e-5f) * gamma[f];
    }
    __syncthreads();
    const float mean = sm_mean[lf];
    const float scale = sm_scale[lf];
    const float bb = beta[f];
    #pragma unroll 4
    for (int b = g * 64; b < g * 64 + 64; b++) {
        const float v = g_hdec[b * H + f];
        g_hn[b * H + f] = (v - mean) * scale + bb;
    }
}

// ---------------- GRU elementwise update (gate order r,z,n) ----------------
__global__ void k_gru_update(int t, const int* __restrict__ trace,
                             const int* __restrict__ choices)
{
    const int b = blockIdx.x;
    const int f = threadIdx.x;
    const int prev = trace[b * T + t];
    const int val  = choices[b * NC + prev];
    const float* cw = g_CWf + (size_t)(prev * NO + val) * G3;
    const float* pc = g_progC + (size_t)b * G3;
    const float* gh = g_gg + (size_t)b * G3;
    const float gxr = cw[f]         + pc[f];
    const float gxz = cw[H + f]     + pc[H + f];
    const float gxn = cw[2 * H + f] + pc[2 * H + f];
    const float r = 1.f / (1.f + expf(-(gxr + gh[f])));
    const float z = 1.f / (1.f + expf(-(gxz + gh[H + f])));
    const float n = tanhf(gxn + r * gh[2 * H + f]);
    const float hnv = g_hn[b * H + f];
    const float hnew = (1.f - z) * n + z * hnv;
    g_hdec[b * H + f] = hnew;
    g_hall[((size_t)t * B + b) * H + f] = hnew;
}

// ---------------- routed prediction heads, grouped by class ----------------
__global__ void k_preds(const int* __restrict__ trace,
                        const float* __restrict__ infW,
                        const float* __restrict__ infb,
                        float* __restrict__ out)
{
    const int t = blockIdx.x;    // 0..T-2
    const int c = blockIdx.y;    // 0..NC-1
    const int tid = threadIdx.x; // 256
    __shared__ int lst[B];
    __shared__ int cnt;
    if (tid == 0) cnt = 0;
    __syncthreads();
    for (int b = tid; b < B; b += 256) {
        if (trace[b * T + t + 1] == c) {
            const int p = atomicAdd(&cnt, 1);
            lst[p] = b;
        }
    }
    __syncthreads();
    const int L = cnt;
    if (L == 0) return;

    if (c == 0) {  // not_ended mask: output zeros
        for (int m = 0; m < L; m++)
            out[((size_t)t * B + lst[m]) * NO + tid] = 0.f;
        return;
    }

    __shared__ float hs[8][H];
    __shared__ float Wsm[256][33];
    const float* Wc = infW + (size_t)c * NO * H;
    const float bi = infb[c * NO + tid];

    for (int m0 = 0; m0 < L; m0 += 8) {
        const int mm = min(8, L - m0);
        for (int idx = tid; idx < mm * H; idx += 256) {
            const int m = idx / H, k = idx % H;
            hs[m][k] = g_hall[((size_t)t * B + lst[m0 + m]) * H + k];
        }
        __syncthreads();
        float acc[8] = {};
        for (int kk = 0; kk < H; kk += 32) {
            #pragma unroll
            for (int j = 0; j < 32; j++) {
                const int lin = j * 256 + tid;
                const int n = lin >> 5, k = lin & 31;
                Wsm[n][k] = Wc[n * H + kk + k];
            }
            __syncthreads();
            #pragma unroll
            for (int k = 0; k < 32; k++) {
                const float w = Wsm[tid][k];
                #pragma unroll
                for (int m = 0; m < 8; m++)
                    acc[m] += w * hs[m][kk + k];
            }
            __syncthreads();
        }
        for (int m = 0; m < mm; m++)
            out[((size_t)t * B + lst[m0 + m]) * NO + tid] = acc[m] + bi;
        __syncthreads();
    }
}

// ---------------- host launcher (graph-capturable; no allocs, no syncs) ----------------
extern "C" void kernel_launch(void* const* d_in, const int* in_sizes, int n_in,
                              void* d_out, int out_size)
{
    const int*   program      = (const int*)d_in[0];
    const int*   plen         = (const int*)d_in[1];
    const int*   trace        = (const int*)d_in[2];
    const int*   choices      = (const int*)d_in[3];
    const float* enc_embed    = (const float*)d_in[4];
    const float* lstm_W_ih    = (const float*)d_in[5];
    const float* lstm_W_hh    = (const float*)d_in[6];
    const float* lstm_b_ih    = (const float*)d_in[7];
    const float* lstm_b_hh    = (const float*)d_in[8];
    const float* h0           = (const float*)d_in[9];
    const float* c0           = (const float*)d_in[10];
    const float* index_embed  = (const float*)d_in[11];
    const float* choice_tab   = (const float*)d_in[12];
    const float* gru_W_ih     = (const float*)d_in[13];
    const float* gru_W_hh     = (const float*)d_in[14];
    const float* gru_b_ih     = (const float*)d_in[15];
    const float* gru_b_hh     = (const float*)d_in[16];
    const float* bn_gamma     = (const float*)d_in[17];
    const float* bn_beta      = (const float*)d_in[18];
    const float* inf_W        = (const float*)d_in[19];
    const float* inf_b        = (const float*)d_in[20];
    const float* h_dec0       = (const float*)d_in[21];
    float* out = (float*)d_out;

    float *ewb, *cwf, *idxc, *progc, *hA, *hB, *hnp, *ggp, *wihp, *bias2p;
    cudaGetSymbolAddress((void**)&ewb,    g_EWb);
    cudaGetSymbolAddress((void**)&cwf,    g_CWf);
    cudaGetSymbolAddress((void**)&idxc,   g_idxC);
    cudaGetSymbolAddress((void**)&progc,  g_progC);
    cudaGetSymbolAddress((void**)&hA,     g_hA);
    cudaGetSymbolAddress((void**)&hB,     g_hB);
    cudaGetSymbolAddress((void**)&hnp,    g_hn);
    cudaGetSymbolAddress((void**)&ggp,    g_gg);
    cudaGetSymbolAddress((void**)&wihp,   g_Wih_p);
    cudaGetSymbolAddress((void**)&bias2p, g_bias2p);

    k_init<<<(B * H + 255) / 256, 256>>>(h0, c0, h_dec0);
    k_permute<<<(G4 * E + 255) / 256, 256>>>(lstm_W_ih, lstm_W_hh, lstm_b_ih, lstm_b_hh);

    // EWb = enc_embed @ Wih_p^T + bias2p   (permuted gate layout)
    sgemm_nt<<<dim3(G4 / 64, (VOC + 63) / 64), 256>>>(
        ewb, enc_embed, E, wihp, E, 0, VOC, G4, E, bias2p);

    // CWf = choice_tables @ W_ih[:, :E]^T + b_ih
    sgemm_nt<<<dim3(G3 / 64, (NC * NO) / 64), 256>>>(
        cwf, choice_tab, E, gru_W_ih, INDC, 0, NC * NO, G3, E, gru_b_ih);

    // idxC = index_embed @ W_ih[:, E+H:]^T
    sgemm_nt<<<dim3(G3 / 64, 1), 256>>>(
        idxc, index_embed, E, gru_W_ih, INDC, H + E, NC, G3, E, nullptr);

    k_cwf_fix<<<(int)(((size_t)NC * NO * G3 + 255) / 256), 256>>>();

    // ---- LSTM encoder: 256 sequential fused steps (ping-pong h buffers) ----
    for (int t = 0; t < P; t++) {
        const float* hin = (t & 1) ? hB : hA;
        float* hout      = (t & 1) ? hA : hB;
        k_lstm_step<<<dim3(G4 / 64, B / 64), 256>>>(hin, hout, t, program, plen);
    }
    // P=256 even -> final hidden lands in g_hA

    // progC = prog_emb @ W_ih[:, E:E+H]^T
    sgemm_nt<<<dim3(G3 / 64, B / 64), 256>>>(
        progc, hA, H, gru_W_ih, INDC, E, B, G3, H, nullptr);

    // ---- GRU decoder: 127 sequential steps ----
    for (int t = 0; t < T - 1; t++) {
        k_bn<<<8, 256>>>(bn_gamma, bn_beta);
        sgemm_nt<<<dim3(G3 / 64, B / 64), 256>>>(
            ggp, hnp, H, gru_W_hh, H, 0, B, G3, H, gru_b_hh);
        k_gru_update<<<B, H>>>(t, trace, choices);
    }

    // ---- routed prediction heads ----
    k_preds<<<dim3(T - 1, NC), 256>>>(trace, inf_W, inf_b, out);

    (void)in_sizes; (void)n_in; (void)out_size;
}

// round 5
// speedup vs baseline: 1.3278x; 1.3278x over previous
#include <cuda_runtime.h>
#include <cstddef>

#define B    512
#define P    256
#define T    128
#define E    300
#define H    256
#define NC   64
#define NO   256
#define VOC  10000
#define G4   1024
#define G3   768
#define G4P  1024
#define INDC 856
#define NBLK 128
#define TPB  256

// ---------------- scratch ----------------
__device__ float g_EWb[VOC * G4];            // enc_embed @ Wih_p^T + bias (4f+g)
__device__ float g_CWf[NC * NO * G4P];       // padded gru input rows (4f+g, dummy gate)
__device__ float g_idxC[NC * G4P];
__device__ float g_progC[B * G4P];
__device__ float g_hsA[B * H], g_hsB[B * H]; // LSTM hidden ping-pong (sorted order)
__device__ float g_c0s[B * H];               // LSTM cell init (sorted)
__device__ float g_hfin[B * H];              // final LSTM hidden (orig order)
__device__ float g_hdA[B * H], g_hdB[B * H]; // GRU hidden ping-pong (orig order)
__device__ float g_hall[(T - 1) * B * H];
__device__ float g_Wih_p[G4 * E];
__device__ float g_Whh_p[G4 * H];
__device__ float g_bias2p[G4];
__device__ float g_gWih_p4[G4P * INDC];
__device__ float g_gWhh_p4[G4P * H];
__device__ float g_gbih_p4[G4P];
__device__ float2 g_bnpart[8 * H];
__device__ int   g_perm[B], g_plen_s[B], g_act[P];
__device__ unsigned g_barA, g_barB;

// ---------------- f32x2 helpers ----------------
union F4 { float4 v; unsigned long long u[2]; };
__device__ __forceinline__ unsigned long long bcast2(float x) {
    unsigned long long r; unsigned u = __float_as_uint(x);
    asm("mov.b64 %0,{%1,%1};" : "=l"(r) : "r"(u)); return r;
}
__device__ __forceinline__ void ffma2(unsigned long long& d, unsigned long long a, unsigned long long b) {
    asm("fma.rn.f32x2 %0, %1, %2, %0;" : "+l"(d) : "l"(a), "l"(b));
}
__device__ __forceinline__ float2 unpack2(unsigned long long v) {
    unsigned lo, hi;
    asm("mov.b64 {%0,%1}, %2;" : "=r"(lo), "=r"(hi) : "l"(v));
    return make_float2(__uint_as_float(lo), __uint_as_float(hi));
}

// ---------------- grid barrier ----------------
__device__ __forceinline__ void gsync(unsigned* bar, unsigned target) {
    __syncthreads();
    if (threadIdx.x == 0) {
        __threadfence();
        asm volatile("red.release.gpu.add.u32 [%0], 1;" :: "l"(bar) : "memory");
        unsigned v; int it = 0;
        do {
            asm volatile("ld.acquire.gpu.b32 %0, [%1];" : "=r"(v) : "l"(bar) : "memory");
            if (v >= target) break;
            if (((++it) & 127) == 0) __nanosleep(64);
        } while (true);
    }
    __syncthreads();
}

__global__ void k_reset() { g_barA = 0; g_barB = 0; }

// ---------------- precompute SGEMM (known-working) ----------------
__global__ void sgemm_nt(float* __restrict__ C, const float* __restrict__ A, int lda,
                         const float* __restrict__ W, int ldw, int woff,
                         int M, int N, int K, const float* __restrict__ bias)
{
    __shared__ float As[16][68];
    __shared__ float Ws[16][68];
    const int tid = threadIdx.x;
    const int tx = tid & 15, ty = tid >> 4;
    const int m0 = blockIdx.y * 64, n0 = blockIdx.x * 64;
    const int lr = tid >> 2, lk = (tid & 3) * 4;
    float acc[4][4] = {};
    for (int kk = 0; kk < K; kk += 16) {
        const int m = m0 + lr;
        const float* ap = A + (size_t)m * lda + kk + lk;
        #pragma unroll
        for (int i = 0; i < 4; i++) {
            const int k = kk + lk + i;
            As[lk + i][lr] = (m < M && k < K) ? ap[i] : 0.f;
        }
        const int n = n0 + lr;
        const float* wp = W + (size_t)n * ldw + woff + kk + lk;
        #pragma unroll
        for (int i = 0; i < 4; i++) {
            const int k = kk + lk + i;
            Ws[lk + i][lr] = (n < N && k < K) ? wp[i] : 0.f;
        }
        __syncthreads();
        #pragma unroll
        for (int kt = 0; kt < 16; kt++) {
            const float4 a4 = *(const float4*)&As[kt][ty * 4];
            const float4 b4 = *(const float4*)&Ws[kt][tx * 4];
            const float av[4] = {a4.x, a4.y, a4.z, a4.w};
            const float bv[4] = {b4.x, b4.y, b4.z, b4.w};
            #pragma unroll
            for (int i = 0; i < 4; i++)
                #pragma unroll
                for (int j = 0; j < 4; j++)
                    acc[i][j] += av[i] * bv[j];
        }
        __syncthreads();
    }
    #pragma unroll
    for (int i = 0; i < 4; i++) {
        const int m = m0 + ty * 4 + i;
        if (m < M)
            #pragma unroll
            for (int j = 0; j < 4; j++) {
                const int n = n0 + tx * 4 + j;
                float v = acc[i][j];
                if (bias) v += bias[n];
                C[(size_t)m * N + n] = v;
            }
    }
}

// ---------------- counting sort by plen (desc) ----------------
__global__ void k_sort(const int* __restrict__ plen)
{
    if (threadIdx.x || blockIdx.x) return;
    int hist[258], suf[258], cur[258];
    for (int v = 0; v <= 257; v++) hist[v] = 0;
    for (int b = 0; b < B; b++) hist[plen[b]]++;
    suf[257] = 0;
    for (int v = 256; v >= 1; v--) suf[v] = suf[v + 1] + hist[v];
    for (int t = 0; t < P; t++) g_act[t] = suf[t + 1];
    for (int v = 1; v <= 256; v++) cur[v] = suf[v + 1];
    for (int b = 0; b < B; b++) {
        const int v = plen[b], pp = cur[v]++;
        g_perm[pp] = b; g_plen_s[pp] = v;
    }
}

// ---------------- weight permutations (gate-interleave, pad) ----------------
__global__ void k_permute_all(const float* __restrict__ lWih, const float* __restrict__ lWhh,
                              const float* __restrict__ lbih, const float* __restrict__ lbhh,
                              const float* __restrict__ gWih, const float* __restrict__ gWhh,
                              const float* __restrict__ gbih)
{
    const int id = blockIdx.x * 256 + threadIdx.x;
    if (id < G4 * E) {
        const int np = id / E, k = id - np * E, f = np >> 2, g = np & 3;
        g_Wih_p[id] = lWih[(g * H + f) * E + k];
    }
    if (id < G4 * H) {
        const int np = id / H, k = id - np * H, f = np >> 2, g = np & 3;
        g_Whh_p[id] = lWhh[(g * H + f) * H + k];
        g_gWhh_p4[id] = (g < 3) ? gWhh[(g * H + f) * H + k] : 0.f;
    }
    if (id < G4) {
        const int f = id >> 2, g = id & 3;
        g_bias2p[id] = lbih[g * H + f] + lbhh[g * H + f];
        g_gbih_p4[id] = (g < 3) ? gbih[g * H + f] : 0.f;
    }
    if (id < G4P * INDC) {
        const int np = id / INDC, k = id - np * INDC, f = np >> 2, g = np & 3;
        g_gWih_p4[id] = (g < 3) ? gWih[(g * H + f) * INDC + k] : 0.f;
    }
}

__global__ void k_init(const float* __restrict__ h0, const float* __restrict__ c0,
                       const float* __restrict__ hd0)
{
    const int i = blockIdx.x * 256 + threadIdx.x;
    if (i < B * H) {
        const int b = i >> 8, f = i & 255, ob = g_perm[b];
        g_hsA[i] = h0[ob * H + f];
        g_c0s[i] = c0[ob * H + f];
        g_hdA[i] = hd0[i];
    }
}

__global__ void k_unsort()
{
    const int i = blockIdx.x * 256 + threadIdx.x;
    if (i < B * H) {
        const int b = i >> 8, f = i & 255;
        g_hfin[g_perm[b] * H + f] = g_hsA[i];
    }
}

__global__ void k_cwf_fix()
{
    const size_t id = (size_t)blockIdx.x * 256 + threadIdx.x;
    if (id >= (size_t)NC * NO * G4P) return;
    const int n = (int)(id & (G4P - 1));
    const int p = (int)(id >> 10) / NO;
    g_CWf[id] += g_idxC[p * G4P + n];
}

__global__ void k_bnpart0(const float* __restrict__ hd0)
{
    const int mb = blockIdx.x, f = threadIdx.x;
    float s = 0.f, s2 = 0.f;
    for (int r = 0; r < 64; r++) {
        const float v = hd0[(mb * 64 + r) * H + f];
        s += v; s2 += v * v;
    }
    g_bnpart[mb * H + f] = make_float2(s, s2);
}

// ---------------- persistent LSTM (256 steps, 1 gsync/step) ----------------
__global__ void __launch_bounds__(TPB, 1)
k_lstm_persist(const int* __restrict__ program)
{
    extern __shared__ float sm[];
    float* Ws = sm;                  // [256][68] (k-major)
    float* As = sm + 256 * 68;       // [64][260] (m-major)
    const int tid = threadIdx.x;
    const int nblk = blockIdx.x & 15, mblk = blockIdx.x >> 4;
    const int n0 = nblk * 64, m0 = mblk * 64;
    const int tx = tid & 15, ty = tid >> 4;
    const int f = (n0 >> 2) + tx;

    for (int q = tid; q < 64 * 64; q += TPB) {
        const int j = q >> 6, kq = q & 63;
        const float4 w = *(const float4*)(g_Whh_p + (size_t)(n0 + j) * H + (kq << 2));
        Ws[(kq * 4 + 0) * 68 + j] = w.x; Ws[(kq * 4 + 1) * 68 + j] = w.y;
        Ws[(kq * 4 + 2) * 68 + j] = w.z; Ws[(kq * 4 + 3) * 68 + j] = w.w;
    }
    int rows[4], ob[4], pl[4];
    float c[4];
    #pragma unroll
    for (int i = 0; i < 4; i++) {
        rows[i] = m0 + ty * 4 + i;
        ob[i] = g_perm[rows[i]];
        pl[i] = g_plen_s[rows[i]];
        c[i] = g_c0s[rows[i] * H + f];
    }
    __syncthreads();

    unsigned tgt = 0;
    for (int t = 0; t < P; t++) {
        const float* hin = (t & 1) ? g_hsB : g_hsA;
        float* hout      = (t & 1) ? g_hsA : g_hsB;
        if (m0 < g_act[t]) {
            for (int q = tid; q < 64 * 64; q += TPB) {
                const int m = q >> 6, kq = q & 63;
                *(float4*)(As + m * 260 + (kq << 2)) =
                    *(const float4*)(hin + (size_t)(m0 + m) * H + (kq << 2));
            }
            __syncthreads();
            unsigned long long acc[4][2] = {};
            #pragma unroll 4
            for (int k = 0; k < H; k++) {
                F4 w; w.v = *(const float4*)(Ws + k * 68 + (tx << 2));
                #pragma unroll
                for (int i = 0; i < 4; i++) {
                    const unsigned long long av = bcast2(As[(ty * 4 + i) * 260 + k]);
                    ffma2(acc[i][0], av, w.u[0]);
                    ffma2(acc[i][1], av, w.u[1]);
                }
            }
            #pragma unroll
            for (int i = 0; i < 4; i++) {
                const int rs = rows[i];
                if (t < pl[i]) {
                    const int pid = __ldg(program + ob[i] * P + t);
                    const float4 ew = *(const float4*)(g_EWb + (size_t)pid * G4 + n0 + (tx << 2));
                    const float2 p0 = unpack2(acc[i][0]);
                    const float2 p1 = unpack2(acc[i][1]);
                    const float gi = p0.x + ew.x, gf = p0.y + ew.y;
                    const float gg = p1.x + ew.z, go = p1.y + ew.w;
                    const float ig = 1.f / (1.f + expf(-gi));
                    const float fg = 1.f / (1.f + expf(-gf));
                    const float og = 1.f / (1.f + expf(-go));
                    c[i] = fg * c[i] + ig * tanhf(gg);
                    hout[rs * H + f] = og * tanhf(c[i]);
                } else {
                    hout[rs * H + f] = hin[rs * H + f];
                }
            }
        } else {
            #pragma unroll
            for (int i = 0; i < 4; i++)
                hout[rows[i] * H + f] = hin[rows[i] * H + f];
        }
        tgt += NBLK;
        gsync(&g_barA, tgt);
    }
}

// ---------------- persistent GRU (127 steps, BN + update fused, 1 gsync/step) ----------------
__global__ void __launch_bounds__(TPB, 1)
k_gru_persist(const int* __restrict__ trace, const int* __restrict__ choices,
              const float* __restrict__ b_hh,
              const float* __restrict__ gamma, const float* __restrict__ beta)
{
    extern __shared__ float sm[];
    float* Ws      = sm;                       // [256][68]
    float* As      = sm + 256 * 68;            // [64][260] normalized hn
    float* s_mean  = sm + 256 * 68 + 64 * 260;
    float* s_scale = s_mean + 256;
    float* s_beta  = s_scale + 256;
    float2* s_red  = (float2*)(s_beta + 256);
    const int tid = threadIdx.x;
    const int nblk = blockIdx.x & 15, mblk = blockIdx.x >> 4;
    const int n0 = nblk * 64, m0 = mblk * 64;
    const int tx = tid & 15, ty = tid >> 4;
    const int f = (n0 >> 2) + tx;

    for (int q = tid; q < 64 * 64; q += TPB) {
        const int j = q >> 6, kq = q & 63;
        const float4 w = *(const float4*)(g_gWhh_p4 + (size_t)(n0 + j) * H + (kq << 2));
        Ws[(kq * 4 + 0) * 68 + j] = w.x; Ws[(kq * 4 + 1) * 68 + j] = w.y;
        Ws[(kq * 4 + 2) * 68 + j] = w.z; Ws[(kq * 4 + 3) * 68 + j] = w.w;
    }
    const float br = b_hh[f], bz = b_hh[H + f], bnb = b_hh[2 * H + f];
    s_beta[tid] = beta[tid];
    int rows[4];
    #pragma unroll
    for (int i = 0; i < 4; i++) rows[i] = m0 + ty * 4 + i;
    __syncthreads();

    unsigned tgt = 0;
    for (int t = 0; t < T - 1; t++) {
        const float* hin = (t & 1) ? g_hdB : g_hdA;
        float* hout      = (t & 1) ? g_hdA : g_hdB;
        {   // finalize BN stats for feature `tid`
            float s = 0.f, s2 = 0.f;
            #pragma unroll
            for (int mb = 0; mb < 8; mb++) {
                const float2 p = g_bnpart[mb * H + tid];
                s += p.x; s2 += p.y;
            }
            const float mean = s * (1.f / 512.f);
            const float var = s2 * (1.f / 512.f) - mean * mean;
            s_mean[tid] = mean;
            s_scale[tid] = rsqrtf(var + 1e-5f) * gamma[tid];
        }
        __syncthreads();
        for (int q = tid; q < 64 * 64; q += TPB) {
            const int m = q >> 6, kq = q & 63, k0 = kq << 2;
            float4 v = *(const float4*)(hin + (size_t)(m0 + m) * H + k0);
            v.x = (v.x - s_mean[k0 + 0]) * s_scale[k0 + 0] + s_beta[k0 + 0];
            v.y = (v.y - s_mean[k0 + 1]) * s_scale[k0 + 1] + s_beta[k0 + 1];
            v.z = (v.z - s_mean[k0 + 2]) * s_scale[k0 + 2] + s_beta[k0 + 2];
            v.w = (v.w - s_mean[k0 + 3]) * s_scale[k0 + 3] + s_beta[k0 + 3];
            *(float4*)(As + m * 260 + k0) = v;
        }
        __syncthreads();
        unsigned long long acc[4][2] = {};
        #pragma unroll 4
        for (int k = 0; k < H; k++) {
            F4 w; w.v = *(const float4*)(Ws + k * 68 + (tx << 2));
            #pragma unroll
            for (int i = 0; i < 4; i++) {
                const unsigned long long av = bcast2(As[(ty * 4 + i) * 260 + k]);
                ffma2(acc[i][0], av, w.u[0]);
                ffma2(acc[i][1], av, w.u[1]);
            }
        }
        float ps = 0.f, ps2 = 0.f;
        #pragma unroll
        for (int i = 0; i < 4; i++) {
            const int b = rows[i];
            const int prev = __ldg(trace + b * T + t);
            const int val  = __ldg(choices + b * NC + prev);
            const float4 cw = *(const float4*)(g_CWf + (size_t)(prev * NO + val) * G4P + n0 + (tx << 2));
            const float4 pc = *(const float4*)(g_progC + (size_t)b * G4P + n0 + (tx << 2));
            const float2 p0 = unpack2(acc[i][0]);
            const float2 p1 = unpack2(acc[i][1]);
            const float r = 1.f / (1.f + expf(-(cw.x + pc.x + p0.x + br)));
            const float z = 1.f / (1.f + expf(-(cw.y + pc.y + p0.y + bz)));
            const float n = tanhf(cw.z + pc.z + r * (p1.x + bnb));
            const float hnv = As[(ty * 4 + i) * 260 + f];
            const float hnew = (1.f - z) * n + z * hnv;
            hout[b * H + f] = hnew;
            g_hall[((size_t)t * B + b) * H + f] = hnew;
            ps += hnew; ps2 += hnew * hnew;
        }
        s_red[tid] = make_float2(ps, ps2);
        __syncthreads();
        if (ty == 0) {
            float s = 0.f, s2 = 0.f;
            #pragma unroll
            for (int j = 0; j < 16; j++) {
                const float2 v = s_red[j * 16 + tx];
                s += v.x; s2 += v.y;
            }
            g_bnpart[mblk * H + f] = make_float2(s, s2);
        }
        tgt += NBLK;
        gsync(&g_barB, tgt);
    }
}

// ---------------- routed prediction heads ----------------
__global__ void k_preds(const int* __restrict__ trace, const float* __restrict__ infW,
                        const float* __restrict__ infb, float* __restrict__ out)
{
    const int t = blockIdx.x, c = blockIdx.y, tid = threadIdx.x;
    __shared__ int lst[B];
    __shared__ int cnt;
    if (tid == 0) cnt = 0;
    __syncthreads();
    for (int b = tid; b < B; b += 256)
        if (trace[b * T + t + 1] == c) lst[atomicAdd(&cnt, 1)] = b;
    __syncthreads();
    const int L = cnt;
    if (L == 0) return;
    if (c == 0) {
        for (int m = 0; m < L; m++)
            out[((size_t)t * B + lst[m]) * NO + tid] = 0.f;
        return;
    }
    __shared__ float hs[8][H];
    __shared__ float Wsm[256][33];
    const float* Wc = infW + (size_t)c * NO * H;
    const float bi = infb[c * NO + tid];
    for (int m0 = 0; m0 < L; m0 += 8) {
        const int mm = min(8, L - m0);
        for (int idx = tid; idx < mm * H; idx += 256)
            hs[idx / H][idx % H] = g_hall[((size_t)t * B + lst[m0 + idx / H]) * H + idx % H];
        __syncthreads();
        float acc[8] = {};
        for (int kk = 0; kk < H; kk += 32) {
            #pragma unroll
            for (int j = 0; j < 32; j++) {
                const int lin = j * 256 + tid;
                Wsm[lin >> 5][lin & 31] = Wc[(lin >> 5) * H + kk + (lin & 31)];
            }
            __syncthreads();
            #pragma unroll
            for (int k = 0; k < 32; k++) {
                const float w = Wsm[tid][k];
                #pragma unroll
                for (int m = 0; m < 8; m++) acc[m] += w * hs[m][kk + k];
            }
            __syncthreads();
        }
        for (int m = 0; m < mm; m++)
            out[((size_t)t * B + lst[m0 + m]) * NO + tid] = acc[m] + bi;
        __syncthreads();
    }
}

// ---------------- host launcher ----------------
extern "C" void kernel_launch(void* const* d_in, const int* in_sizes, int n_in,
                              void* d_out, int out_size)
{
    const int*   program   = (const int*)d_in[0];
    const int*   plen      = (const int*)d_in[1];
    const int*   trace     = (const int*)d_in[2];
    const int*   choices   = (const int*)d_in[3];
    const float* enc_embed = (const float*)d_in[4];
    const float* lWih      = (const float*)d_in[5];
    const float* lWhh      = (const float*)d_in[6];
    const float* lbih      = (const float*)d_in[7];
    const float* lbhh      = (const float*)d_in[8];
    const float* h0        = (const float*)d_in[9];
    const float* c0        = (const float*)d_in[10];
    const float* idx_emb   = (const float*)d_in[11];
    const float* ch_tab    = (const float*)d_in[12];
    const float* gWih      = (const float*)d_in[13];
    const float* gWhh      = (const float*)d_in[14];
    const float* gbih      = (const float*)d_in[15];
    const float* gbhh      = (const float*)d_in[16];
    const float* bn_g      = (const float*)d_in[17];
    const float* bn_b      = (const float*)d_in[18];
    const float* inf_W     = (const float*)d_in[19];
    const float* inf_b     = (const float*)d_in[20];
    const float* hd0       = (const float*)d_in[21];
    float* out = (float*)d_out;

    float *ewb, *cwf, *idxc, *progc, *wihp, *b2p, *gwp, *gbp, *hfin;
    cudaGetSymbolAddress((void**)&ewb,   g_EWb);
    cudaGetSymbolAddress((void**)&cwf,   g_CWf);
    cudaGetSymbolAddress((void**)&idxc,  g_idxC);
    cudaGetSymbolAddress((void**)&progc, g_progC);
    cudaGetSymbolAddress((void**)&wihp,  g_Wih_p);
    cudaGetSymbolAddress((void**)&b2p,   g_bias2p);
    cudaGetSymbolAddress((void**)&gwp,   g_gWih_p4);
    cudaGetSymbolAddress((void**)&gbp,   g_gbih_p4);
    cudaGetSymbolAddress((void**)&hfin,  g_hfin);

    const int SMEM = (256 * 68 + 64 * 260 + 3 * 256) * 4 + 256 * 8;
    cudaFuncSetAttribute(k_lstm_persist, cudaFuncAttributeMaxDynamicSharedMemorySize, SMEM);
    cudaFuncSetAttribute(k_gru_persist,  cudaFuncAttributeMaxDynamicSharedMemorySize, SMEM);

    k_reset<<<1, 1>>>();
    k_sort<<<1, 1>>>(plen);
    k_permute_all<<<(G4P * INDC + 255) / 256, 256>>>(lWih, lWhh, lbih, lbhh, gWih, gWhh, gbih);
    k_init<<<(B * H + 255) / 256, 256>>>(h0, c0, hd0);

    sgemm_nt<<<dim3(G4 / 64, (VOC + 63) / 64), 256>>>(ewb, enc_embed, E, wihp, E, 0, VOC, G4, E, b2p);
    sgemm_nt<<<dim3(G4P / 64, (NC * NO) / 64), 256>>>(cwf, ch_tab, E, gwp, INDC, 0, NC * NO, G4P, E, gbp);
    sgemm_nt<<<dim3(G4P / 64, 1), 256>>>(idxc, idx_emb, E, gwp, INDC, H + E, NC, G4P, E, nullptr);
    k_cwf_fix<<<(int)(((size_t)NC * NO * G4P + 255) / 256), 256>>>();

    k_lstm_persist<<<NBLK, TPB, SMEM>>>(program);
    k_unsort<<<(B * H + 255) / 256, 256>>>();

    sgemm_nt<<<dim3(G4P / 64, B / 64), 256>>>(progc, hfin, H, gwp, INDC, E, B, G4P, H, nullptr);

    k_bnpart0<<<8, 256>>>(hd0);
    k_gru_persist<<<NBLK, TPB, SMEM>>>(trace, choices, gbhh, bn_g, bn_b);

    k_preds<<<dim3(T - 1, NC), 256>>>(trace, inf_W, inf_b, out);

    (void)in_sizes; (void)n_in; (void)out_size;
}